// round 2
// baseline (speedup 1.0000x reference)
#include <cuda_runtime.h>
#include <cstdint>

// Problem constants (from reference)
#define NROW0 50
#define NROW1 50
#define NROW2 50
#define NPAIR (NROW0 * NROW1)       // 2500 (d0,d1) combos
#define TROW  512                   // t row = 16 (k) x 32 (r2) floats
#define G1LEN 4096                  // core1 row: 32*4*32
#define G0LEN 128                   // core0 row: 1*4*32
#define G2LEN 256                   // core2 row: 32*8
#define EMBD  128
#define G2_SMEM_FLOATS (NROW2 * G2LEN)   // 12800 floats = 51.2 KB

// Scratch: precomputed t_table[p][k*32+r] for p = d0*50+d1 (5.12 MB, L2-resident)
__device__ float g_t_table[NPAIR * TROW];

// ---------------------------------------------------------------------------
// Stage 1: t_table[p] = core0[d0] (4x32) @ core1[d1] (32x128)   (41 M FMA total)
// Output layout j = x*128 + y*32 + s  ==  k*32 + s with k = x*4+y.
// ---------------------------------------------------------------------------
__global__ void __launch_bounds__(128) tt_stage1(const float* __restrict__ core0,
                                                 const float* __restrict__ core1)
{
    __shared__ float s_g1[G1LEN];
    __shared__ float s_g0[G0LEN];
    const int p   = blockIdx.x;
    const int d0  = p / NROW1;
    const int d1  = p - d0 * NROW1;
    const int tid = threadIdx.x;

    const float* g1 = core1 + (size_t)d1 * G1LEN;
    #pragma unroll
    for (int t = tid; t < G1LEN; t += 128) s_g1[t] = g1[t];
    s_g0[tid] = core0[d0 * G0LEN + tid];
    __syncthreads();

    float a0 = 0.f, a1 = 0.f, a2 = 0.f, a3 = 0.f;
    #pragma unroll
    for (int r = 0; r < 32; ++r) {
        const float g1v = s_g1[r * 128 + tid];   // conflict-free (consecutive lanes)
        a0 = fmaf(s_g0[r],      g1v, a0);        // broadcast
        a1 = fmaf(s_g0[32 + r], g1v, a1);
        a2 = fmaf(s_g0[64 + r], g1v, a2);
        a3 = fmaf(s_g0[96 + r], g1v, a3);
    }
    float* o = g_t_table + (size_t)p * TROW;
    o[tid]       = a0;   // x=0
    o[tid + 128] = a1;   // x=1
    o[tid + 256] = a2;   // x=2
    o[tid + 384] = a3;   // x=3
}

// ---------------------------------------------------------------------------
// Stage 2: persistent bag kernel.
// Thread tid owns output element e = k*8+z (k=tid>>3, z=tid&7).
//   emb[k,z] = sum_r t_table[p][k*32+r] * core2[d2][r*8+z]
// core2 is staged in SMEM transposed per-row to [z][r] with XOR-swizzled 16B
// chunks: element (z, r) stored at d2*256 + z*32 + ((r/4)^z)*4 + (r%4).
// -> LDS.128 wavefront: 8 distinct z -> 8 distinct 16B bank-groups (conflict
//    free), 4-way broadcast across the 4 k-values sharing each z.
// Cache-table bag is fused (coalesced 512B row gathers, 4x unrolled).
// NOTE: all index arrays are int32 (JAX x64 disabled downcasts int64->int32).
// ---------------------------------------------------------------------------
__global__ void __launch_bounds__(128) bag_kernel(
    const int*   __restrict__ indices,
    const int*   __restrict__ offsets,
    const int*   __restrict__ cached_indices,
    const int*   __restrict__ cached_offsets,
    const float* __restrict__ core2,
    const float* __restrict__ cache_table,
    float*       __restrict__ out,
    int num_bags)
{
    extern __shared__ float s_g2t[];   // 12800 floats
    const int tid = threadIdx.x;

    // Stage core2 (coalesced global read, swizzled smem scatter) — once per block.
    for (int u = tid; u < G2_SMEM_FLOATS; u += 128) {
        const int d2  = u >> 8;
        const int rem = u & 255;
        const int r   = rem >> 3;
        const int z   = rem & 7;
        const int pos = (d2 << 8) + (z << 5) + ((((r >> 2) ^ z) & 7) << 2) + (r & 3);
        s_g2t[pos] = core2[u];
    }
    __syncthreads();

    const int k = tid >> 3;
    const int z = tid & 7;

    for (int b = blockIdx.x; b < num_bags; b += gridDim.x) {
        // ---- TT bag ----
        const int i0 = offsets[b];
        const int i1 = offsets[b + 1];
        float a0 = 0.f, a1 = 0.f, a2 = 0.f, a3 = 0.f;
        for (int i = i0; i < i1; ++i) {
            const int idx = indices[i];            // < 125000, broadcast load
            const int p   = idx / 50;              // d0*50 + d1
            const int d2  = idx - p * 50;
            const float4* tr  = (const float4*)(g_t_table + ((size_t)p << 9) + (k << 5));
            const float4* g2b = (const float4*)(s_g2t + (d2 << 8) + (z << 5));
            #pragma unroll
            for (int c = 0; c < 8; ++c) {
                const float4 tv = tr[c];           // LDG.128, L2 hit (5.12MB table)
                const float4 gv = g2b[c ^ z];      // LDS.128, conflict-free
                a0 = fmaf(tv.x, gv.x, a0);
                a1 = fmaf(tv.y, gv.y, a1);
                a2 = fmaf(tv.z, gv.z, a2);
                a3 = fmaf(tv.w, gv.w, a3);
            }
        }
        const float tt = (a0 + a1) + (a2 + a3);

        // ---- cached-table bag (coalesced row gather) ----
        const int j0 = cached_offsets[b];
        const int j1 = cached_offsets[b + 1];
        float cacc = 0.f;
        int j = j0;
        for (; j + 4 <= j1; j += 4) {
            const int c0 = cached_indices[j];
            const int c1 = cached_indices[j + 1];
            const int c2 = cached_indices[j + 2];
            const int c3 = cached_indices[j + 3];
            const float v0 = cache_table[(size_t)c0 * EMBD + tid];
            const float v1 = cache_table[(size_t)c1 * EMBD + tid];
            const float v2 = cache_table[(size_t)c2 * EMBD + tid];
            const float v3 = cache_table[(size_t)c3 * EMBD + tid];
            cacc += (v0 + v1) + (v2 + v3);
        }
        for (; j < j1; ++j)
            cacc += cache_table[(size_t)cached_indices[j] * EMBD + tid];

        out[(size_t)b * EMBD + tid] = tt + cacc;
    }
}

// ---------------------------------------------------------------------------
extern "C" void kernel_launch(void* const* d_in, const int* in_sizes, int n_in,
                              void* d_out, int out_size)
{
    const int*   indices        = (const int*)d_in[0];
    const int*   offsets        = (const int*)d_in[1];
    const int*   cached_indices = (const int*)d_in[2];
    const int*   cached_offsets = (const int*)d_in[3];
    const float* core0          = (const float*)d_in[4];
    const float* core1          = (const float*)d_in[5];
    const float* core2          = (const float*)d_in[6];
    const float* cache_table    = (const float*)d_in[7];
    float* out = (float*)d_out;

    const int num_bags = out_size / EMBD;   // 4096

    // Stage 1: build t_table (2500 blocks, trivial cost).
    tt_stage1<<<NPAIR, 128>>>(core0, core1);

    // Stage 2: persistent bag kernel, ~4 blocks/SM at 51.2 KB dynamic smem.
    const size_t smem = G2_SMEM_FLOATS * sizeof(float);   // 51200 B > 48KB default
    static int attr_set = 0;
    if (!attr_set) {
        cudaFuncSetAttribute(bag_kernel,
                             cudaFuncAttributeMaxDynamicSharedMemorySize, (int)smem);
        attr_set = 1;
    }
    int grid = 608;                 // ~4 per SM on 148-152 SMs
    if (grid > num_bags) grid = num_bags;
    bag_kernel<<<grid, 128, smem>>>(indices, offsets, cached_indices, cached_offsets,
                                    core2, cache_table, out, num_bags);
}